// round 9
// baseline (speedup 1.0000x reference)
#include <cuda_runtime.h>
#include <cuda_bf16.h>

// Problem constants
#define BB 8
#define NN 512
#define DD 64
#define EE 32

#define NBLK 512              // total blocks (covers proj rows AND edge tiles)
#define JT 64                 // edge: j's per block (8 warps x 8 j)
#define SS 8                  // i-splits
#define IT (NN / SS)          // 64 i-rows per edge tile

// Scratch (allocation-free rule -> __device__ globals)
__device__ float g_src [BB * NN * EE];        // src[b,n,e]
__device__ float g_dstb[BB * NN * EE];        // dst[b,n,e] + be[e]
__device__ float g_part[BB * NN * SS];        // partial[b,j,s]

// Monotonic barrier state (graph-replay safe: never reset)
__device__ unsigned long long g_gen;
__device__ unsigned long long g_bar0;
__device__ unsigned long long g_bar1;

// ---- packed fp32 pair helpers (sm_103a FADD2/FFMA2 via PTX f32x2) ----------
union F2U { unsigned long long u; float2 f; };

__device__ __forceinline__ unsigned long long add2(unsigned long long a,
                                                   unsigned long long b) {
    unsigned long long r;
    asm("add.rn.f32x2 %0, %1, %2;" : "=l"(r) : "l"(a), "l"(b));
    return r;
}
__device__ __forceinline__ unsigned long long fma2(unsigned long long a,
                                                   unsigned long long b,
                                                   unsigned long long c) {
    unsigned long long r;
    asm("fma.rn.f32x2 %0, %1, %2, %3;" : "=l"(r) : "l"(a), "l"(b), "l"(c));
    return r;
}

// ---------------------------------------------------------------------------
// Fused kernel: proj -> grid barrier -> edge -> grid barrier -> final reduce
// 512 blocks x 256 threads, 24 KB smem (overlaid between phases).
// Co-residency: 8 blocks/SM capacity vs 3.5 needed -> spin barrier is safe.
// ---------------------------------------------------------------------------
__global__ __launch_bounds__(256) void fused_kernel(
    const float* __restrict__ x,
    const float* __restrict__ We,
    const float* __restrict__ be,
    const float* __restrict__ Wr,
    const float* __restrict__ br,
    float* __restrict__ out)
{
    __shared__ __align__(16) char sraw[24576];
    __shared__ unsigned long long s_gen;

    const int tid  = threadIdx.x;
    const int bid  = blockIdx.x;
    const int lane = tid & 31;
    const int w    = tid >> 5;

    if (tid == 0) s_gen = atomicAdd(&g_gen, 1ull) / NBLK;   // launch generation

    // ===== Phase 1: proj rows [bid*8, bid*8+8) ==============================
    {
        float* Wsh = (float*)sraw;                 // [2*DD][EE] = 16 KB
        float* xs  = (float*)(sraw + 16384);       // [8][DD]    =  2 KB
        const int row0 = bid * 8;

        #pragma unroll
        for (int k = 0; k < 4; k++)
            ((float4*)Wsh)[k * 256 + tid] = ((const float4*)We)[k * 256 + tid];
        if (tid < 128)
            ((float4*)xs)[tid] = ((const float4*)(x + row0 * DD))[tid];
        __syncthreads();

        // warp w owns row w; computes both src and dst projections
        float accs = 0.0f;
        float accd = be[lane];
        #pragma unroll 8
        for (int d4 = 0; d4 < DD; d4 += 4) {
            float4 xv = *(const float4*)&xs[w * DD + d4];   // broadcast LDS.128
            #pragma unroll
            for (int k = 0; k < 4; k++) {
                float xd = (&xv.x)[k];
                accs = fmaf(xd, Wsh[(d4 + k) * EE + lane], accs);
                accd = fmaf(xd, Wsh[(DD + d4 + k) * EE + lane], accd);
            }
        }
        g_src [(row0 + w) * EE + lane] = accs;
        g_dstb[(row0 + w) * EE + lane] = accd;
    }

    // ===== Grid barrier 0 ===================================================
    __threadfence();
    __syncthreads();
    const unsigned long long gen = s_gen;
    if (tid == 0) {
        atomicAdd(&g_bar0, 1ull);
        volatile unsigned long long* p = &g_bar0;
        const unsigned long long target = (gen + 1) * (unsigned long long)NBLK;
        while (*p < target) { }
    }
    __syncthreads();
    __threadfence();

    // ===== Phase 2: edge reduce (R7 e-packed f32x2 body) ====================
    {
        const int jb = bid & 7;                    // NN/JT = 8
        const int b  = (bid >> 3) & 7;             // BB = 8
        const int s  = bid >> 6;                   // SS = 8
        const int le = lane & 15;                  // e-pair index (e = 2*le)
        const int jg = lane >> 4;                  // j-group within warp

        float* src_sh = (float*)sraw;              // 8 KB
        float* wr_sh  = (float*)(sraw + 8192);     // 8 KB
        float* dst_sh = (float*)(sraw + 16384);    // 8 KB

        {
            const float4* dst_g = (const float4*)(g_dstb + (b * NN + jb * JT) * EE);
            const float4* src_g = (const float4*)(g_src  + (b * NN + s  * IT) * EE);
            const float4* wr_g  = (const float4*)(Wr + s * IT * EE);
            #pragma unroll
            for (int k = 0; k < 2; k++) {
                ((float4*)dst_sh)[k * 256 + tid] = dst_g[k * 256 + tid];
                ((float4*)src_sh)[k * 256 + tid] = src_g[k * 256 + tid];
                ((float4*)wr_sh )[k * 256 + tid] = wr_g [k * 256 + tid];
            }
        }
        __syncthreads();

        const int jl0 = w * 8 + jg * 4;
        F2U dreg2[4], acc2[4];
        #pragma unroll
        for (int r = 0; r < 4; r++) {
            dreg2[r].f = *(const float2*)&dst_sh[(jl0 + r) * EE + 2 * le];
            acc2[r].u  = 0ull;
        }

        #pragma unroll 8
        for (int i = 0; i < IT; i++) {
            F2U sv2, wv2;
            sv2.f = *(const float2*)&src_sh[i * EE + 2 * le];
            wv2.f = *(const float2*)&wr_sh [i * EE + 2 * le];
            #pragma unroll
            for (int r = 0; r < 4; r++) {
                F2U t; t.u = add2(sv2.u, dreg2[r].u);       // FADD2
                t.f.x = fmaxf(t.f.x, 0.0f);                 // FMNMX (alu pipe)
                t.f.y = fmaxf(t.f.y, 0.0f);
                acc2[r].u = fma2(t.u, wv2.u, acc2[r].u);    // FFMA2
            }
        }

        float acc[4];
        #pragma unroll
        for (int r = 0; r < 4; r++) {
            acc[r] = acc2[r].f.x + acc2[r].f.y;
            #pragma unroll
            for (int off = 8; off; off >>= 1)
                acc[r] += __shfl_xor_sync(0xFFFFFFFFu, acc[r], off);
        }

        if (le == 0) {                             // lanes 0 and 16 write
            const int j = jb * JT + jl0;
            #pragma unroll
            for (int r = 0; r < 4; r++)
                g_part[(b * NN + j + r) * SS + s] = acc[r];
        }
    }

    // ===== Grid barrier 1 (blocks >=16 arrive and exit; 0..15 spin) =========
    __threadfence();
    __syncthreads();
    if (tid == 0) atomicAdd(&g_bar1, 1ull);
    if (bid >= 16) return;

    if (tid == 0) {
        volatile unsigned long long* p = &g_bar1;
        const unsigned long long target = (gen + 1) * (unsigned long long)NBLK;
        while (*p < target) { }
    }
    __syncthreads();
    __threadfence();

    // ===== Phase 3: final reduce, 16 blocks x 256 threads = 4096 outputs ====
    {
        const int idx = bid * 256 + tid;           // b*N + j
        const float4* p4 = (const float4*)(g_part + idx * SS);
        float4 a = p4[0];
        float4 c = p4[1];
        out[idx] = (a.x + a.y) + (a.z + a.w) + (c.x + c.y) + (c.z + c.w) + br[0];
    }
}

// ---------------------------------------------------------------------------
// launch: ONE kernel
// ---------------------------------------------------------------------------
extern "C" void kernel_launch(void* const* d_in, const int* in_sizes, int n_in,
                              void* d_out, int out_size)
{
    const float* x  = (const float*)d_in[0];   // (8,512,64)
    const float* We = (const float*)d_in[1];   // (128,32)
    const float* be = (const float*)d_in[2];   // (32,)
    const float* Wr = (const float*)d_in[3];   // (16384,1)
    const float* br = (const float*)d_in[4];   // (1,)
    float* out = (float*)d_out;                // (8,512,1)

    fused_kernel<<<NBLK, 256>>>(x, We, be, Wr, br, out);
}